// round 3
// baseline (speedup 1.0000x reference)
#include <cuda_runtime.h>
#include <cuda_bf16.h>

// ---------------------------------------------------------------------------
// DIN forward, fp32, f32x2-packed FMA.
// Kernel 1: per-batch-row attention (896 thr, 28 warps) -> g_interest[B][64]
// Kernel 2: batched final MLP (16 rows per CTA, 2 CTA/SM) -> d_out[B]
// ---------------------------------------------------------------------------

#define B_ROWS 4096
#define T_LEN  200
#define TP     224          // padded T (28 warps * 8)
#define E_DIM  64
#define NTHR1  896

__device__ float g_interest[B_ROWS * E_DIM];

__device__ __forceinline__ float2 fma2(float2 a, float2 b, float2 c) {
    float2 d;
    asm("fma.rn.f32x2 %0, %1, %2, %3;"
        : "=l"(*(unsigned long long*)&d)
        : "l"(*(unsigned long long*)&a),
          "l"(*(unsigned long long*)&b),
          "l"(*(unsigned long long*)&c));
    return d;
}

// ---- smem layout (floats) for kernel 1 ----
#define OFF_XT   0                 // 64 x 224            = 14336
#define OFF_W12  14336             // 4096 float2 (dup)   = 8192 floats
#define OFF_H1   22528             // 64 x 226            = 14464
#define OFF_W2D  36992             // 2048 float2 (dup)   = 4096 floats
#define OFF_Q    41088             // 64
#define OFF_QC   41152             // 64
#define OFF_SC   41216             // 224
#define OFF_WG   41440             // 224
#define OFF_RED  41664             // 32
#define OFF_SV   41696             // 2
#define OFF_MSK  41698             // 224 bytes (uchar)
#define SMEM1_BYTES (167040)

__global__ void __launch_bounds__(NTHR1, 1)
din_attn_kernel(const int* __restrict__ tgt,
                const int* __restrict__ hist,
                const int* __restrict__ mask,          // bool shipped as int32
                const float* __restrict__ item_table,
                const float* __restrict__ w1, const float* __restrict__ b1,
                const float* __restrict__ w2, const float* __restrict__ b2,
                const float* __restrict__ wo, const float* __restrict__ bo)
{
    extern __shared__ float sm[];
    float*  XT  = sm + OFF_XT;
    float2* W12 = (float2*)(sm + OFF_W12);
    float*  H1  = sm + OFF_H1;
    float2* W2D = (float2*)(sm + OFF_W2D);
    float*  Q   = sm + OFF_Q;
    float*  QC  = sm + OFF_QC;
    float*  SC  = sm + OFF_SC;
    float*  WG  = sm + OFF_WG;
    float*  RED = sm + OFF_RED;
    float*  SV  = sm + OFF_SV;
    unsigned char* MSK = (unsigned char*)(sm + OFF_MSK);

    const int b    = blockIdx.x;
    const int tid  = threadIdx.x;
    const int lane = tid & 31;
    const int warp = tid >> 5;

    // ---- phase 0: load q, mask, W2 (duplicated), gather keys transposed ----
    if (tid < E_DIM) Q[tid] = item_table[(long)tgt[b] * E_DIM + tid];
    if (tid < TP)    MSK[tid] = (tid < T_LEN) ? (unsigned char)(mask[b * T_LEN + tid] != 0)
                                              : (unsigned char)0;

    for (int i = tid; i < 64 * 32; i += NTHR1) {
        float v = w2[i];
        W2D[i] = make_float2(v, v);
    }

    // keys: XT[e][t] (stride TP). Lanes walk consecutive t -> conflict-free STS.
    for (int i = tid; i < 16 * TP; i += NTHR1) {
        int t = i % TP;
        int f = i / TP;      // float4 chunk of the embedding (0..15)
        float4 v = make_float4(0.f, 0.f, 0.f, 0.f);
        if (t < T_LEN) {
            int row = hist[b * T_LEN + t];
            v = *(const float4*)(item_table + (long)row * E_DIM + 4 * f);
        }
        XT[(4 * f + 0) * TP + t] = v.x;
        XT[(4 * f + 1) * TP + t] = v.y;
        XT[(4 * f + 2) * TP + t] = v.z;
        XT[(4 * f + 3) * TP + t] = v.w;
    }
    __syncthreads();

    // ---- phase 1: fold weights.  W12[k][j] = (Wk+Wd)[k][j] + q[k]*Wp[k][j]
    //      qc[j] = b1[j] + sum_e q[e]*(Wq-Wd)[e][j]
    for (int i = tid; i < 4096; i += NTHR1) {
        int k = i >> 6;
        float v = w1[i] + w1[8192 + i] + Q[k] * w1[12288 + i];
        W12[i] = make_float2(v, v);
    }
    if (tid < E_DIM) {
        float s = b1[tid];
        #pragma unroll 8
        for (int e = 0; e < 64; ++e)
            s += Q[e] * (w1[4096 + e * 64 + tid] - w1[8192 + e * 64 + tid]);
        QC[tid] = s;
    }
    __syncthreads();

    // ---- phase 2: GEMM1  h1[m][j] = relu( sum_k XT[k][m]*W12[k][j] + qc[j] )
    // warp owns m in [8w, 8w+8), lane owns columns {lane, lane+32}
    const int mb = warp * 8;
    float2 acc0[4], acc1[4];
    #pragma unroll
    for (int p = 0; p < 4; ++p) { acc0[p] = make_float2(0.f, 0.f); acc1[p] = make_float2(0.f, 0.f); }

    #pragma unroll 4
    for (int k = 0; k < 64; ++k) {
        float2 bb0 = W12[k * 64 + lane];
        float2 bb1 = W12[k * 64 + lane + 32];
        const float* xr = XT + k * TP + mb;
        #pragma unroll
        for (int p = 0; p < 4; ++p) {
            float2 a = *(const float2*)(xr + 2 * p);
            acc0[p] = fma2(a, bb0, acc0[p]);
            acc1[p] = fma2(a, bb1, acc1[p]);
        }
    }
    {
        float qa = QC[lane], qb = QC[lane + 32];
        #pragma unroll
        for (int p = 0; p < 4; ++p) {
            float2 r0 = make_float2(fmaxf(acc0[p].x + qa, 0.f), fmaxf(acc0[p].y + qa, 0.f));
            float2 r1 = make_float2(fmaxf(acc1[p].x + qb, 0.f), fmaxf(acc1[p].y + qb, 0.f));
            *(float2*)(H1 + lane * 226 + mb + 2 * p)        = r0;
            *(float2*)(H1 + (lane + 32) * 226 + mb + 2 * p) = r1;
        }
    }
    __syncthreads();

    // ---- phase 3: GEMM2 (64->32) + score reduction ----
    float2 acc[4];
    #pragma unroll
    for (int p = 0; p < 4; ++p) acc[p] = make_float2(0.f, 0.f);

    #pragma unroll 4
    for (int k = 0; k < 64; ++k) {
        float2 bb = W2D[k * 32 + lane];
        const float* hr = H1 + k * 226 + mb;
        #pragma unroll
        for (int p = 0; p < 4; ++p) {
            float2 a = *(const float2*)(hr + 2 * p);
            acc[p] = fma2(a, bb, acc[p]);
        }
    }
    {
        float bb2 = b2[lane];
        float wol = wo[lane];
        float bos = bo[0];
        #pragma unroll
        for (int p = 0; p < 4; ++p) {
            float hx = fmaxf(acc[p].x + bb2, 0.f) * wol;
            float hy = fmaxf(acc[p].y + bb2, 0.f) * wol;
            #pragma unroll
            for (int off = 16; off > 0; off >>= 1) {
                hx += __shfl_xor_sync(0xffffffffu, hx, off);
                hy += __shfl_xor_sync(0xffffffffu, hy, off);
            }
            if (lane == 0) {
                int m = mb + 2 * p;
                SC[m]     = MSK[m]     ? hx + bos : -1e9f;
                SC[m + 1] = MSK[m + 1] ? hy + bos : -1e9f;
            }
        }
    }
    __syncthreads();

    // ---- phase 4: softmax over 224 (pads carry -1e9 -> weight 0) ----
    {
        float s = (tid < TP) ? SC[tid] : -3.4e38f;
        #pragma unroll
        for (int off = 16; off > 0; off >>= 1)
            s = fmaxf(s, __shfl_xor_sync(0xffffffffu, s, off));
        if (lane == 0) RED[warp] = s;
    }
    __syncthreads();
    if (warp == 0) {
        float m = (lane < 7) ? RED[lane] : -3.4e38f;   // only warps 0..6 held tid<224
        #pragma unroll
        for (int off = 4; off > 0; off >>= 1)
            m = fmaxf(m, __shfl_xor_sync(0xffffffffu, m, off));
        if (lane == 0) SV[0] = m;
    }
    __syncthreads();
    {
        float smax = SV[0];
        float e = 0.f;
        if (tid < TP) {
            e = expf(SC[tid] - smax);
            WG[tid] = e;
        }
        #pragma unroll
        for (int off = 16; off > 0; off >>= 1)
            e += __shfl_xor_sync(0xffffffffu, e, off);
        if (lane == 0) RED[warp] = e;
    }
    __syncthreads();
    if (warp == 0) {
        float t2 = (lane < 7) ? RED[lane] : 0.f;
        #pragma unroll
        for (int off = 4; off > 0; off >>= 1)
            t2 += __shfl_xor_sync(0xffffffffu, t2, off);
        if (lane == 0) SV[1] = t2;
    }
    __syncthreads();

    // ---- phase 5: interest[e] = sum_t wgt[t]*k_t[e] / ssum ----
    // warps 0..15: warp w owns e in [4w, 4w+4); lanes walk distinct t
    if (warp < 16) {
        const int e0 = warp * 4;
        float s0 = 0.f, s1 = 0.f, s2 = 0.f, s3 = 0.f;
        #pragma unroll
        for (int i = 0; i < 7; ++i) {
            int t = lane + 32 * i;
            float wv = WG[t];
            s0 += wv * XT[(e0 + 0) * TP + t];
            s1 += wv * XT[(e0 + 1) * TP + t];
            s2 += wv * XT[(e0 + 2) * TP + t];
            s3 += wv * XT[(e0 + 3) * TP + t];
        }
        #pragma unroll
        for (int off = 16; off > 0; off >>= 1) {
            s0 += __shfl_xor_sync(0xffffffffu, s0, off);
            s1 += __shfl_xor_sync(0xffffffffu, s1, off);
            s2 += __shfl_xor_sync(0xffffffffu, s2, off);
            s3 += __shfl_xor_sync(0xffffffffu, s3, off);
        }
        if (lane == 0) {
            float invs = 1.0f / SV[1];
            float* gi = g_interest + (long)b * E_DIM + e0;
            gi[0] = s0 * invs;
            gi[1] = s1 * invs;
            gi[2] = s2 * invs;
            gi[3] = s3 * invs;
        }
    }
}

// ---------------------------------------------------------------------------
// Kernel 2: final MLP, 16 batch rows per CTA, 256 threads, 2 CTAs/SM.
// feat[272] = [user(64), ctx(64), q(64), interest(64), dense(16)]
// ---------------------------------------------------------------------------
#define BTILE 16
#define SMEM2_FLOATS (272*BTILE + 256*18 + 64)
#define SMEM2_BYTES  (SMEM2_FLOATS * 4)

__global__ void __launch_bounds__(256, 2)
din_mlp_kernel(const int* __restrict__ tgt,
               const int* __restrict__ sf,
               const float* __restrict__ dense,
               const float* __restrict__ item_table,
               const float* __restrict__ user_table,
               const float* __restrict__ ctx_table,
               const float* __restrict__ w1, const float* __restrict__ b1,
               const float* __restrict__ w2, const float* __restrict__ b2,
               const float* __restrict__ ow, const float* __restrict__ ob,
               float* __restrict__ out)
{
    extern __shared__ float sm[];
    float* At  = sm;                       // [272][16]
    float* H1t = sm + 272 * BTILE;         // [256][18]
    float* R   = sm + 272 * BTILE + 256 * 18;  // [4][16]

    const int b0   = blockIdx.x * BTILE;
    const int tid  = threadIdx.x;
    const int lane = tid & 31;
    const int warp = tid >> 5;

    // build transposed feature tile At[k][b]
    for (int i = tid; i < 272 * BTILE; i += 256) {
        int bb = i & (BTILE - 1);
        int k  = i / BTILE;
        int gb = b0 + bb;
        float v;
        if (k < 64)        v = user_table[(long)sf[gb * 2] * 64 + k];
        else if (k < 128)  v = ctx_table[(long)sf[gb * 2 + 1] * 64 + (k - 64)];
        else if (k < 192)  v = item_table[(long)tgt[gb] * 64 + (k - 128)];
        else if (k < 256)  v = g_interest[(long)gb * 64 + (k - 192)];
        else               v = dense[gb * 16 + (k - 256)];
        At[k * BTILE + bb] = v;
    }
    __syncthreads();

    // layer 1: 272 -> 256, thread owns output channel n=tid, all 16 b packed
    {
        float2 acc[8];
        #pragma unroll
        for (int p = 0; p < 8; ++p) acc[p] = make_float2(0.f, 0.f);
        #pragma unroll 4
        for (int k = 0; k < 272; ++k) {
            float wv = w1[k * 256 + tid];
            float2 bb = make_float2(wv, wv);
            const float* ar = At + k * BTILE;
            #pragma unroll
            for (int p = 0; p < 8; ++p)
                acc[p] = fma2(*(const float2*)(ar + 2 * p), bb, acc[p]);
        }
        float bias = b1[tid];
        #pragma unroll
        for (int p = 0; p < 8; ++p) {
            float2 r = make_float2(fmaxf(acc[p].x + bias, 0.f), fmaxf(acc[p].y + bias, 0.f));
            *(float2*)(H1t + tid * 18 + 2 * p) = r;
        }
    }
    __syncthreads();

    // layer 2: 256 -> 128, then dot with out_w, reduce over channels
    if (tid < 128) {
        float2 acc[8];
        #pragma unroll
        for (int p = 0; p < 8; ++p) acc[p] = make_float2(0.f, 0.f);
        #pragma unroll 4
        for (int k = 0; k < 256; ++k) {
            float wv = w2[k * 128 + tid];
            float2 bb = make_float2(wv, wv);
            const float* hr = H1t + k * 18;
            #pragma unroll
            for (int p = 0; p < 8; ++p)
                acc[p] = fma2(*(const float2*)(hr + 2 * p), bb, acc[p]);
        }
        float bias = b2[tid];
        float owl  = ow[tid];
        #pragma unroll
        for (int p = 0; p < 8; ++p) {
            float hx = fmaxf(acc[p].x + bias, 0.f) * owl;
            float hy = fmaxf(acc[p].y + bias, 0.f) * owl;
            #pragma unroll
            for (int off = 16; off > 0; off >>= 1) {
                hx += __shfl_xor_sync(0xffffffffu, hx, off);
                hy += __shfl_xor_sync(0xffffffffu, hy, off);
            }
            if (lane == 0) {
                R[warp * BTILE + 2 * p]     = hx;
                R[warp * BTILE + 2 * p + 1] = hy;
            }
        }
    }
    __syncthreads();
    if (tid < BTILE) {
        float s = R[tid] + R[BTILE + tid] + R[2 * BTILE + tid] + R[3 * BTILE + tid] + ob[0];
        out[b0 + tid] = s;
    }
}

// ---------------------------------------------------------------------------
extern "C" void kernel_launch(void* const* d_in, const int* in_sizes, int n_in,
                              void* d_out, int out_size)
{
    const int*           tgt   = (const int*)d_in[0];
    const int*           hist  = (const int*)d_in[1];
    const int*           mask  = (const int*)d_in[2];   // bool -> int32
    const int*           sf    = (const int*)d_in[3];
    const float*         dense = (const float*)d_in[4];
    const float*         item_table = (const float*)d_in[5];
    const float*         user_table = (const float*)d_in[6];
    const float*         ctx_table  = (const float*)d_in[7];
    const float*         att_w1 = (const float*)d_in[8];
    const float*         att_b1 = (const float*)d_in[9];
    const float*         att_w2 = (const float*)d_in[10];
    const float*         att_b2 = (const float*)d_in[11];
    const float*         att_wo = (const float*)d_in[12];
    const float*         att_bo = (const float*)d_in[13];
    const float*         mlp_w1 = (const float*)d_in[14];
    const float*         mlp_b1 = (const float*)d_in[15];
    const float*         mlp_w2 = (const float*)d_in[16];
    const float*         mlp_b2 = (const float*)d_in[17];
    const float*         out_w  = (const float*)d_in[18];
    const float*         out_b  = (const float*)d_in[19];
    float*               out    = (float*)d_out;

    cudaFuncSetAttribute(din_attn_kernel, cudaFuncAttributeMaxDynamicSharedMemorySize, SMEM1_BYTES);
    cudaFuncSetAttribute(din_mlp_kernel,  cudaFuncAttributeMaxDynamicSharedMemorySize, SMEM2_BYTES);

    din_attn_kernel<<<B_ROWS, NTHR1, SMEM1_BYTES>>>(
        tgt, hist, mask, item_table,
        att_w1, att_b1, att_w2, att_b2, att_wo, att_bo);

    din_mlp_kernel<<<B_ROWS / BTILE, 256, SMEM2_BYTES>>>(
        tgt, sf, dense, item_table, user_table, ctx_table,
        mlp_w1, mlp_b1, mlp_w2, mlp_b2, out_w, out_b, out);
}

// round 4
// speedup vs baseline: 1.1156x; 1.1156x over previous
#include <cuda_runtime.h>
#include <cuda_bf16.h>

// ---------------------------------------------------------------------------
// DIN forward, fp32, f32x2-packed FMA. Crossbar-lean smem layout:
//  - B operands stored un-duplicated (LDS.32 spread, reg-dup)
//  - A operands read as float4 broadcasts (LDS.128)
// ---------------------------------------------------------------------------

#define B_ROWS 4096
#define T_LEN  200
#define TP     224          // padded T (28 warps * 8)
#define E_DIM  64
#define NTHR1  896

__device__ float g_interest[B_ROWS * E_DIM];

__device__ __forceinline__ float2 fma2(float2 a, float2 b, float2 c) {
    float2 d;
    asm("fma.rn.f32x2 %0, %1, %2, %3;"
        : "=l"(*(unsigned long long*)&d)
        : "l"(*(unsigned long long*)&a),
          "l"(*(unsigned long long*)&b),
          "l"(*(unsigned long long*)&c));
    return d;
}

// ---- smem layout (float offsets) for kernel 1 ----
#define OFF_XT   0                 // 64 x 224  = 14336
#define OFF_W12  14336             // 64 x 64   = 4096
#define OFF_H1   18432             // 64 x 228  = 14592
#define OFF_W2   33024             // 64 x 32   = 2048
#define OFF_Q    35072             // 64
#define OFF_QC   35136             // 64
#define OFF_SC   35200             // 224
#define OFF_WG   35424             // 224
#define OFF_RED  35648             // 32
#define OFF_SV   35680             // 4
#define OFF_MSK  35684             // 224 bytes (uchar) = 56 floats
#define SMEM1_BYTES (35744 * 4)

__global__ void __launch_bounds__(NTHR1, 1)
din_attn_kernel(const int* __restrict__ tgt,
                const int* __restrict__ hist,
                const int* __restrict__ mask,          // bool shipped as int32
                const float* __restrict__ item_table,
                const float* __restrict__ w1, const float* __restrict__ b1,
                const float* __restrict__ w2, const float* __restrict__ b2,
                const float* __restrict__ wo, const float* __restrict__ bo)
{
    extern __shared__ float sm[];
    float*  XT  = sm + OFF_XT;
    float*  W12 = sm + OFF_W12;
    float*  H1  = sm + OFF_H1;
    float*  W2s = sm + OFF_W2;
    float*  Q   = sm + OFF_Q;
    float*  QC  = sm + OFF_QC;
    float*  SC  = sm + OFF_SC;
    float*  WG  = sm + OFF_WG;
    float*  RED = sm + OFF_RED;
    float*  SV  = sm + OFF_SV;
    unsigned char* MSK = (unsigned char*)(sm + OFF_MSK);

    const int b    = blockIdx.x;
    const int tid  = threadIdx.x;
    const int lane = tid & 31;
    const int warp = tid >> 5;

    // ---- phase 0: load q, mask, W2 (plain), gather keys transposed ----
    if (tid < E_DIM) Q[tid] = item_table[(long)tgt[b] * E_DIM + tid];
    if (tid < TP)    MSK[tid] = (tid < T_LEN) ? (unsigned char)(mask[b * T_LEN + tid] != 0)
                                              : (unsigned char)0;

    for (int i = tid; i < 64 * 32; i += NTHR1) W2s[i] = w2[i];

    // keys: XT[e][t] (stride TP). Lanes walk consecutive t -> conflict-free STS.
    for (int i = tid; i < 16 * TP; i += NTHR1) {
        int t = i % TP;
        int f = i / TP;      // float4 chunk of the embedding (0..15)
        float4 v = make_float4(0.f, 0.f, 0.f, 0.f);
        if (t < T_LEN) {
            int row = hist[b * T_LEN + t];
            v = *(const float4*)(item_table + (long)row * E_DIM + 4 * f);
        }
        XT[(4 * f + 0) * TP + t] = v.x;
        XT[(4 * f + 1) * TP + t] = v.y;
        XT[(4 * f + 2) * TP + t] = v.z;
        XT[(4 * f + 3) * TP + t] = v.w;
    }
    __syncthreads();

    // ---- phase 1: fold weights.  W12[k][j] = (Wk+Wd)[k][j] + q[k]*Wp[k][j]
    //      qc[j] = b1[j] + sum_e q[e]*(Wq-Wd)[e][j]
    for (int i = tid; i < 4096; i += NTHR1) {
        int k = i >> 6;
        W12[i] = w1[i] + w1[8192 + i] + Q[k] * w1[12288 + i];
    }
    if (tid < E_DIM) {
        float s = b1[tid];
        #pragma unroll 8
        for (int e = 0; e < 64; ++e)
            s += Q[e] * (w1[4096 + e * 64 + tid] - w1[8192 + e * 64 + tid]);
        QC[tid] = s;
    }
    __syncthreads();

    // ---- phase 2: GEMM1  h1[m][j] = relu( sum_k XT[k][m]*W12[k][j] + qc[j] )
    // warp owns m in [8w, 8w+8), lane owns columns {lane, lane+32}
    const int mb = warp * 8;
    float2 acc0[4], acc1[4];
    #pragma unroll
    for (int p = 0; p < 4; ++p) { acc0[p] = make_float2(0.f, 0.f); acc1[p] = make_float2(0.f, 0.f); }

    #pragma unroll 4
    for (int k = 0; k < 64; ++k) {
        float b0s = W12[k * 64 + lane];
        float b1s = W12[k * 64 + lane + 32];
        float2 bb0 = make_float2(b0s, b0s);
        float2 bb1 = make_float2(b1s, b1s);
        const float4* xr4 = (const float4*)(XT + k * TP + mb);
        float4 aA = xr4[0];
        float4 aB = xr4[1];
        acc0[0] = fma2(make_float2(aA.x, aA.y), bb0, acc0[0]);
        acc1[0] = fma2(make_float2(aA.x, aA.y), bb1, acc1[0]);
        acc0[1] = fma2(make_float2(aA.z, aA.w), bb0, acc0[1]);
        acc1[1] = fma2(make_float2(aA.z, aA.w), bb1, acc1[1]);
        acc0[2] = fma2(make_float2(aB.x, aB.y), bb0, acc0[2]);
        acc1[2] = fma2(make_float2(aB.x, aB.y), bb1, acc1[2]);
        acc0[3] = fma2(make_float2(aB.z, aB.w), bb0, acc0[3]);
        acc1[3] = fma2(make_float2(aB.z, aB.w), bb1, acc1[3]);
    }
    {
        float qa = QC[lane], qb = QC[lane + 32];
        #pragma unroll
        for (int p = 0; p < 4; ++p) {
            float2 r0 = make_float2(fmaxf(acc0[p].x + qa, 0.f), fmaxf(acc0[p].y + qa, 0.f));
            float2 r1 = make_float2(fmaxf(acc1[p].x + qb, 0.f), fmaxf(acc1[p].y + qb, 0.f));
            *(float2*)(H1 + lane * 228 + mb + 2 * p)        = r0;
            *(float2*)(H1 + (lane + 32) * 228 + mb + 2 * p) = r1;
        }
    }
    __syncthreads();

    // ---- phase 3: GEMM2 (64->32) + score reduction ----
    float2 acc[4];
    #pragma unroll
    for (int p = 0; p < 4; ++p) acc[p] = make_float2(0.f, 0.f);

    #pragma unroll 4
    for (int k = 0; k < 64; ++k) {
        float bs = W2s[k * 32 + lane];
        float2 bb = make_float2(bs, bs);
        const float4* hr4 = (const float4*)(H1 + k * 228 + mb);
        float4 aA = hr4[0];
        float4 aB = hr4[1];
        acc[0] = fma2(make_float2(aA.x, aA.y), bb, acc[0]);
        acc[1] = fma2(make_float2(aA.z, aA.w), bb, acc[1]);
        acc[2] = fma2(make_float2(aB.x, aB.y), bb, acc[2]);
        acc[3] = fma2(make_float2(aB.z, aB.w), bb, acc[3]);
    }
    {
        float bb2 = b2[lane];
        float wol = wo[lane];
        float bos = bo[0];
        #pragma unroll
        for (int p = 0; p < 4; ++p) {
            float hx = fmaxf(acc[p].x + bb2, 0.f) * wol;
            float hy = fmaxf(acc[p].y + bb2, 0.f) * wol;
            #pragma unroll
            for (int off = 16; off > 0; off >>= 1) {
                hx += __shfl_xor_sync(0xffffffffu, hx, off);
                hy += __shfl_xor_sync(0xffffffffu, hy, off);
            }
            if (lane == 0) {
                int m = mb + 2 * p;
                SC[m]     = MSK[m]     ? hx + bos : -1e9f;
                SC[m + 1] = MSK[m + 1] ? hy + bos : -1e9f;
            }
        }
    }
    __syncthreads();

    // ---- phase 4: softmax over 224 (pads carry -1e9 -> weight 0) ----
    {
        float s = (tid < TP) ? SC[tid] : -3.4e38f;
        #pragma unroll
        for (int off = 16; off > 0; off >>= 1)
            s = fmaxf(s, __shfl_xor_sync(0xffffffffu, s, off));
        if (lane == 0) RED[warp] = s;
    }
    __syncthreads();
    if (warp == 0) {
        float m = (lane < 7) ? RED[lane] : -3.4e38f;   // warps 0..6 held tid<224
        #pragma unroll
        for (int off = 4; off > 0; off >>= 1)
            m = fmaxf(m, __shfl_xor_sync(0xffffffffu, m, off));
        if (lane == 0) SV[0] = m;
    }
    __syncthreads();
    {
        float smax = SV[0];
        float e = 0.f;
        if (tid < TP) {
            e = expf(SC[tid] - smax);
            WG[tid] = e;
        }
        #pragma unroll
        for (int off = 16; off > 0; off >>= 1)
            e += __shfl_xor_sync(0xffffffffu, e, off);
        if (lane == 0) RED[warp] = e;
    }
    __syncthreads();
    if (warp == 0) {
        float t2 = (lane < 7) ? RED[lane] : 0.f;
        #pragma unroll
        for (int off = 4; off > 0; off >>= 1)
            t2 += __shfl_xor_sync(0xffffffffu, t2, off);
        if (lane == 0) SV[1] = t2;
    }
    __syncthreads();

    // ---- phase 5: interest[e] = sum_t wgt[t]*k_t[e] / ssum ----
    if (warp < 16) {
        const int e0 = warp * 4;
        float s0 = 0.f, s1 = 0.f, s2 = 0.f, s3 = 0.f;
        #pragma unroll
        for (int i = 0; i < 7; ++i) {
            int t = lane + 32 * i;
            float wv = WG[t];
            s0 += wv * XT[(e0 + 0) * TP + t];
            s1 += wv * XT[(e0 + 1) * TP + t];
            s2 += wv * XT[(e0 + 2) * TP + t];
            s3 += wv * XT[(e0 + 3) * TP + t];
        }
        #pragma unroll
        for (int off = 16; off > 0; off >>= 1) {
            s0 += __shfl_xor_sync(0xffffffffu, s0, off);
            s1 += __shfl_xor_sync(0xffffffffu, s1, off);
            s2 += __shfl_xor_sync(0xffffffffu, s2, off);
            s3 += __shfl_xor_sync(0xffffffffu, s3, off);
        }
        if (lane == 0) {
            float invs = 1.0f / SV[1];
            float* gi = g_interest + (long)b * E_DIM + e0;
            gi[0] = s0 * invs;
            gi[1] = s1 * invs;
            gi[2] = s2 * invs;
            gi[3] = s3 * invs;
        }
    }
}

// ---------------------------------------------------------------------------
// Kernel 2: final MLP, 8 batch rows per CTA, 256 threads, up to 4 CTAs/SM.
// feat[272] = [user(64), ctx(64), q(64), interest(64), dense(16)]
// ---------------------------------------------------------------------------
#define BTILE 8
#define H1T_STRIDE 12
#define SMEM2_FLOATS (272*BTILE + 256*H1T_STRIDE + 32)
#define SMEM2_BYTES  (SMEM2_FLOATS * 4)

__global__ void __launch_bounds__(256, 4)
din_mlp_kernel(const int* __restrict__ tgt,
               const int* __restrict__ sf,
               const float* __restrict__ dense,
               const float* __restrict__ item_table,
               const float* __restrict__ user_table,
               const float* __restrict__ ctx_table,
               const float* __restrict__ w1, const float* __restrict__ b1,
               const float* __restrict__ w2, const float* __restrict__ b2,
               const float* __restrict__ ow, const float* __restrict__ ob,
               float* __restrict__ out)
{
    extern __shared__ float sm[];
    float* At  = sm;                               // [272][8]
    float* H1t = sm + 272 * BTILE;                 // [256][12]
    float* R   = sm + 272 * BTILE + 256 * H1T_STRIDE; // [8][4]

    const int b0   = blockIdx.x * BTILE;
    const int tid  = threadIdx.x;
    const int lane = tid & 31;
    const int warp = tid >> 5;

    // build transposed feature tile At[k][b]
    for (int i = tid; i < 272 * BTILE; i += 256) {
        int bb = i & (BTILE - 1);
        int k  = i / BTILE;
        int gb = b0 + bb;
        float v;
        if (k < 64)        v = user_table[(long)sf[gb * 2] * 64 + k];
        else if (k < 128)  v = ctx_table[(long)sf[gb * 2 + 1] * 64 + (k - 64)];
        else if (k < 192)  v = item_table[(long)tgt[gb] * 64 + (k - 128)];
        else if (k < 256)  v = g_interest[(long)gb * 64 + (k - 192)];
        else               v = dense[gb * 16 + (k - 256)];
        At[k * BTILE + bb] = v;
    }
    __syncthreads();

    // layer 1: 272 -> 256, thread owns output channel n=tid, all 8 b packed
    {
        float2 acc[4];
        #pragma unroll
        for (int p = 0; p < 4; ++p) acc[p] = make_float2(0.f, 0.f);
        #pragma unroll 4
        for (int k = 0; k < 272; ++k) {
            float wv = w1[k * 256 + tid];
            float2 bb = make_float2(wv, wv);
            const float4* ar4 = (const float4*)(At + k * BTILE);
            float4 aA = ar4[0];
            float4 aB = ar4[1];
            acc[0] = fma2(make_float2(aA.x, aA.y), bb, acc[0]);
            acc[1] = fma2(make_float2(aA.z, aA.w), bb, acc[1]);
            acc[2] = fma2(make_float2(aB.x, aB.y), bb, acc[2]);
            acc[3] = fma2(make_float2(aB.z, aB.w), bb, acc[3]);
        }
        float bias = b1[tid];
        #pragma unroll
        for (int p = 0; p < 4; ++p) {
            float2 r = make_float2(fmaxf(acc[p].x + bias, 0.f), fmaxf(acc[p].y + bias, 0.f));
            *(float2*)(H1t + tid * H1T_STRIDE + 2 * p) = r;
        }
    }
    __syncthreads();

    // layer 2: 256 -> 128; thread owns channel n = tid&127 and batch-half (tid>>7)
    {
        const int n    = tid & 127;
        const int half = tid >> 7;           // 0: b 0..3, 1: b 4..7
        float2 acc[2];
        acc[0] = make_float2(0.f, 0.f);
        acc[1] = make_float2(0.f, 0.f);
        #pragma unroll 4
        for (int k = 0; k < 256; ++k) {
            float wv = w2[k * 128 + n];
            float2 bb = make_float2(wv, wv);
            float4 h = *(const float4*)(H1t + k * H1T_STRIDE + half * 4);
            acc[0] = fma2(make_float2(h.x, h.y), bb, acc[0]);
            acc[1] = fma2(make_float2(h.z, h.w), bb, acc[1]);
        }
        float bias = b2[n];
        float owl  = ow[n];
        float s0 = fmaxf(acc[0].x + bias, 0.f) * owl;
        float s1 = fmaxf(acc[0].y + bias, 0.f) * owl;
        float s2 = fmaxf(acc[1].x + bias, 0.f) * owl;
        float s3 = fmaxf(acc[1].y + bias, 0.f) * owl;
        #pragma unroll
        for (int off = 16; off > 0; off >>= 1) {
            s0 += __shfl_xor_sync(0xffffffffu, s0, off);
            s1 += __shfl_xor_sync(0xffffffffu, s1, off);
            s2 += __shfl_xor_sync(0xffffffffu, s2, off);
            s3 += __shfl_xor_sync(0xffffffffu, s3, off);
        }
        if (lane == 0) {
            R[warp * 4 + 0] = s0;
            R[warp * 4 + 1] = s1;
            R[warp * 4 + 2] = s2;
            R[warp * 4 + 3] = s3;
        }
    }
    __syncthreads();
    if (tid < BTILE) {
        int bi   = tid & 3;
        int grp  = (tid >> 2) * 4;           // warps 0..3 for b 0..3; 4..7 for b 4..7
        float s = R[(grp + 0) * 4 + bi] + R[(grp + 1) * 4 + bi]
                + R[(grp + 2) * 4 + bi] + R[(grp + 3) * 4 + bi] + ob[0];
        out[b0 + tid] = s;
    }
}

// ---------------------------------------------------------------------------
extern "C" void kernel_launch(void* const* d_in, const int* in_sizes, int n_in,
                              void* d_out, int out_size)
{
    const int*           tgt   = (const int*)d_in[0];
    const int*           hist  = (const int*)d_in[1];
    const int*           mask  = (const int*)d_in[2];   // bool -> int32
    const int*           sf    = (const int*)d_in[3];
    const float*         dense = (const float*)d_in[4];
    const float*         item_table = (const float*)d_in[5];
    const float*         user_table = (const float*)d_in[6];
    const float*         ctx_table  = (const float*)d_in[7];
    const float*         att_w1 = (const float*)d_in[8];
    const float*         att_b1 = (const float*)d_in[9];
    const float*         att_w2 = (const float*)d_in[10];
    const float*         att_b2 = (const float*)d_in[11];
    const float*         att_wo = (const float*)d_in[12];
    const float*         att_bo = (const float*)d_in[13];
    const float*         mlp_w1 = (const float*)d_in[14];
    const float*         mlp_b1 = (const float*)d_in[15];
    const float*         mlp_w2 = (const float*)d_in[16];
    const float*         mlp_b2 = (const float*)d_in[17];
    const float*         out_w  = (const float*)d_in[18];
    const float*         out_b  = (const float*)d_in[19];
    float*               out    = (float*)d_out;

    cudaFuncSetAttribute(din_attn_kernel, cudaFuncAttributeMaxDynamicSharedMemorySize, SMEM1_BYTES);

    din_attn_kernel<<<B_ROWS, NTHR1, SMEM1_BYTES>>>(
        tgt, hist, mask, item_table,
        att_w1, att_b1, att_w2, att_b2, att_wo, att_bo);

    din_mlp_kernel<<<B_ROWS / BTILE, 256, SMEM2_BYTES>>>(
        tgt, sf, dense, item_table, user_table, ctx_table,
        mlp_w1, mlp_b1, mlp_w2, mlp_b2, out_w, out_b, out);
}